// round 1
// baseline (speedup 1.0000x reference)
#include <cuda_runtime.h>

#define T_LEN 512
#define BATCH 1024
#define INF   32
#define H     64
#define OUTF  32
#define BPB   8                 // batches per block
#define NBLK  (BATCH / BPB)     // 128 blocks -> 1 per SM, single wave
#define NTHR  (BPB * 16)        // 128 threads: 16 threads per batch, 4 j's each

struct Smem {
    float W1T[INF][H];   // W1T[i][j]  = Wih1[j][i]
    float Wh1T[H][H];    // Wh1T[k][j] = Whh1[j][k]
    float W2T[H][H];     // W2T[k][j]  = Wih2[j][k]
    float Wh2T[H][H];    // Wh2T[k][j] = Whh2[j][k]
    float h1[BPB][H];
    float h2[BPB][H];
    float xs[2][BPB][INF];
};

__device__ __forceinline__ float fast_tanh(float x) {
    // tanh(x) = (e^{2x}-1)/(e^{2x}+1), via MUFU ex2/rcp. ~1e-7 abs error.
    float cx = fminf(fmaxf(x, -15.f), 15.f);
    float e;
    asm("ex2.approx.f32 %0, %1;" : "=f"(e) : "f"(cx * 2.8853900817779268f));
    float r;
    asm("rcp.approx.f32 %0, %1;" : "=f"(r) : "f"(e + 1.f));
    return (e - 1.f) * r;
}

__global__ void __launch_bounds__(NTHR, 1)
rnn_fused_kernel(const float* __restrict__ x,
                 const float* __restrict__ Wih1, const float* __restrict__ Whh1,
                 const float* __restrict__ bih1, const float* __restrict__ bhh1,
                 const float* __restrict__ Wih2, const float* __restrict__ Whh2,
                 const float* __restrict__ bih2, const float* __restrict__ bhh2,
                 const float* __restrict__ Wfc1, const float* __restrict__ bfc1,
                 const float* __restrict__ Wfc2, const float* __restrict__ bfc2,
                 float* __restrict__ out)
{
    extern __shared__ float smem_raw[];
    Smem* s = reinterpret_cast<Smem*>(smem_raw);
    const int tid = threadIdx.x;

    // ---- Load weights into smem, transposed to [k][j] ----
    for (int idx = tid; idx < H * INF; idx += NTHR) {
        int j = idx / INF, i = idx % INF;
        s->W1T[i][j] = Wih1[idx];
    }
    for (int idx = tid; idx < H * H; idx += NTHR) {
        int j = idx / H, k = idx % H;
        s->Wh1T[k][j] = Whh1[idx];
        s->W2T[k][j]  = Wih2[idx];
        s->Wh2T[k][j] = Whh2[idx];
    }

    const int b  = tid >> 4;          // local batch 0..7
    const int jg = tid & 15;          // j-group 0..15
    const int j4 = jg * 4;
    const int bg = blockIdx.x * BPB + b;   // global batch

    float bias1[4], bias2[4];
#pragma unroll
    for (int u = 0; u < 4; u++) {
        bias1[u] = bih1[j4 + u] + bhh1[j4 + u];
        bias2[u] = bih2[j4 + u] + bhh2[j4 + u];
    }

    // init states & first x tile
    *(float4*)&s->h1[b][j4] = make_float4(0.f, 0.f, 0.f, 0.f);
    *(float4*)&s->h2[b][j4] = make_float4(0.f, 0.f, 0.f, 0.f);
    const float* xb = x + (size_t)bg * T_LEN * INF;
    {
        float2 x0 = *(const float2*)(xb + jg * 2);
        s->xs[0][b][jg * 2]     = x0.x;
        s->xs[0][b][jg * 2 + 1] = x0.y;
    }
    __syncthreads();

    int buf = 0;
    for (int t = 0; t < T_LEN; t++) {
        // prefetch x for t+1 (coalesced 128B per batch half-warp)
        float2 xn = make_float2(0.f, 0.f);
        if (t + 1 < T_LEN) xn = *(const float2*)(xb + (t + 1) * INF + jg * 2);

        // ---------- layer 1: a = x@Wih1^T + h1@Whh1^T + b ----------
        float a0 = bias1[0], a1 = bias1[1], a2 = bias1[2], a3 = bias1[3];
#pragma unroll
        for (int i = 0; i < INF; i += 4) {
            float4 xv = *(const float4*)&s->xs[buf][b][i];
#pragma unroll
            for (int u = 0; u < 4; u++) {
                float xu = (&xv.x)[u];
                float4 w = *(const float4*)&s->W1T[i + u][j4];
                a0 = fmaf(xu, w.x, a0); a1 = fmaf(xu, w.y, a1);
                a2 = fmaf(xu, w.z, a2); a3 = fmaf(xu, w.w, a3);
            }
        }
#pragma unroll
        for (int k = 0; k < H; k += 4) {
            float4 hv = *(const float4*)&s->h1[b][k];
#pragma unroll
            for (int u = 0; u < 4; u++) {
                float hu = (&hv.x)[u];
                float4 w = *(const float4*)&s->Wh1T[k + u][j4];
                a0 = fmaf(hu, w.x, a0); a1 = fmaf(hu, w.y, a1);
                a2 = fmaf(hu, w.z, a2); a3 = fmaf(hu, w.w, a3);
            }
        }
        float n0 = fast_tanh(a0), n1 = fast_tanh(a1);
        float n2 = fast_tanh(a2), n3 = fast_tanh(a3);
        __syncwarp();                                   // old h1 reads done
        *(float4*)&s->h1[b][j4] = make_float4(n0, n1, n2, n3);
        __syncwarp();                                   // new h1 visible

        // ---------- layer 2: a = h1@Wih2^T + h2@Whh2^T + b ----------
        a0 = bias2[0]; a1 = bias2[1]; a2 = bias2[2]; a3 = bias2[3];
#pragma unroll
        for (int k = 0; k < H; k += 4) {
            float4 hv = *(const float4*)&s->h1[b][k];
#pragma unroll
            for (int u = 0; u < 4; u++) {
                float hu = (&hv.x)[u];
                float4 w = *(const float4*)&s->W2T[k + u][j4];
                a0 = fmaf(hu, w.x, a0); a1 = fmaf(hu, w.y, a1);
                a2 = fmaf(hu, w.z, a2); a3 = fmaf(hu, w.w, a3);
            }
        }
#pragma unroll
        for (int k = 0; k < H; k += 4) {
            float4 hv = *(const float4*)&s->h2[b][k];
#pragma unroll
            for (int u = 0; u < 4; u++) {
                float hu = (&hv.x)[u];
                float4 w = *(const float4*)&s->Wh2T[k + u][j4];
                a0 = fmaf(hu, w.x, a0); a1 = fmaf(hu, w.y, a1);
                a2 = fmaf(hu, w.z, a2); a3 = fmaf(hu, w.w, a3);
            }
        }
        n0 = fast_tanh(a0); n1 = fast_tanh(a1);
        n2 = fast_tanh(a2); n3 = fast_tanh(a3);
        __syncwarp();                                   // old h2 reads done
        *(float4*)&s->h2[b][j4] = make_float4(n0, n1, n2, n3);
        s->xs[buf ^ 1][b][jg * 2]     = xn.x;           // stage next x
        s->xs[buf ^ 1][b][jg * 2 + 1] = xn.y;
        __syncwarp();
        buf ^= 1;
    }

    // ---------- FC head: z = relu(h2@Wfc1^T + b); out = z@Wfc2^T + b ----------
    {
        float acc[4];
#pragma unroll
        for (int u = 0; u < 4; u++) acc[u] = bfc1[j4 + u];
#pragma unroll
        for (int k = 0; k < H; k += 4) {
            float4 hv = *(const float4*)&s->h2[b][k];
#pragma unroll
            for (int u = 0; u < 4; u++) {
                float4 w = *(const float4*)&Wfc1[(j4 + u) * H + k];
                acc[u] += hv.x * w.x + hv.y * w.y + hv.z * w.z + hv.w * w.w;
            }
        }
        __syncwarp();
        float4 z;
        z.x = fmaxf(acc[0], 0.f); z.y = fmaxf(acc[1], 0.f);
        z.z = fmaxf(acc[2], 0.f); z.w = fmaxf(acc[3], 0.f);
        *(float4*)&s->h1[b][j4] = z;    // reuse h1 buffer for z
        __syncwarp();

        const int o0 = jg * 2, o1 = jg * 2 + 1;
        float r0 = bfc2[o0], r1 = bfc2[o1];
#pragma unroll
        for (int k = 0; k < H; k += 4) {
            float4 zv = *(const float4*)&s->h1[b][k];
            float4 w0 = *(const float4*)&Wfc2[o0 * H + k];
            float4 w1 = *(const float4*)&Wfc2[o1 * H + k];
            r0 += zv.x * w0.x + zv.y * w0.y + zv.z * w0.z + zv.w * w0.w;
            r1 += zv.x * w1.x + zv.y * w1.y + zv.z * w1.z + zv.w * w1.w;
        }
        out[bg * OUTF + o0] = r0;
        out[bg * OUTF + o1] = r1;
    }
}

extern "C" void kernel_launch(void* const* d_in, const int* in_sizes, int n_in,
                              void* d_out, int out_size)
{
    (void)in_sizes; (void)n_in; (void)out_size;
    const float* x    = (const float*)d_in[0];
    const float* Wih1 = (const float*)d_in[1];
    const float* Whh1 = (const float*)d_in[2];
    const float* bih1 = (const float*)d_in[3];
    const float* bhh1 = (const float*)d_in[4];
    const float* Wih2 = (const float*)d_in[5];
    const float* Whh2 = (const float*)d_in[6];
    const float* bih2 = (const float*)d_in[7];
    const float* bhh2 = (const float*)d_in[8];
    const float* Wfc1 = (const float*)d_in[9];
    const float* bfc1 = (const float*)d_in[10];
    const float* Wfc2 = (const float*)d_in[11];
    const float* bfc2 = (const float*)d_in[12];
    float* out = (float*)d_out;

    size_t smem = sizeof(Smem);
    cudaFuncSetAttribute(rnn_fused_kernel,
                         cudaFuncAttributeMaxDynamicSharedMemorySize, (int)smem);
    rnn_fused_kernel<<<NBLK, NTHR, smem>>>(x, Wih1, Whh1, bih1, bhh1,
                                           Wih2, Whh2, bih2, bhh2,
                                           Wfc1, bfc1, Wfc2, bfc2, out);
}